// round 4
// baseline (speedup 1.0000x reference)
#include <cuda_runtime.h>

#define NB    512      // batch
#define NEE   100000   // entities
#define NRR   400      // relations
#define NA    256      // actions
#define ENT_D 200
#define REL_D 200
#define HIST_D 400
#define ADIM_D 400

// ---------------- scratch (device globals; no allocation allowed) ----------------
__device__ __align__(16) float g_C1[NB * 800];        // [E | H | Q]
__device__ __align__(16) float g_P[NB * ENT_D];       // pred_emb gather
__device__ __align__(16) float g_alpha_in[NB * 400];  // [rel_sum | NR*pred]
__device__ __align__(16) float g_relK[NRR * REL_D];   // relation_emb @ W4^T + b4
__device__ __align__(16) float g_rel_sum[REL_D];
__device__ __align__(16) float g_X[NB * ADIM_D];      // relu(l1)
__device__ __align__(16) float g_XV[NB * 600];        // [X2 (400) | V_A (200)]
__device__ __align__(16) float g_PEI[NB * REL_D];     // pred_ent_info
__device__ __align__(16) float g_AB[NB * 400];        // [alpha (200) | beta (200)]
__device__ __align__(16) float g_ATT[NB * REL_D];     // Watt projection

// ---------------- warp/block reduction helpers ----------------
__device__ __forceinline__ float warp_max(float v) {
#pragma unroll
    for (int o = 16; o; o >>= 1) v = fmaxf(v, __shfl_xor_sync(0xffffffffu, v, o));
    return v;
}
__device__ __forceinline__ float warp_sum(float v) {
#pragma unroll
    for (int o = 16; o; o >>= 1) v += __shfl_xor_sync(0xffffffffu, v, o);
    return v;
}

// block reduce over 256 threads (8 warps). red must have >= 8 floats.
__device__ __forceinline__ float block_max256(float v, float* red, int t) {
    v = warp_max(v);
    if ((t & 31) == 0) red[t >> 5] = v;
    __syncthreads();
    if (t < 8) {
        float x = red[t];
#pragma unroll
        for (int o = 4; o; o >>= 1) x = fmaxf(x, __shfl_xor_sync(0xffu, x, o));
        if (t == 0) red[0] = x;
    }
    __syncthreads();
    float r = red[0];
    __syncthreads();
    return r;
}
__device__ __forceinline__ float block_sum256(float v, float* red, int t) {
    v = warp_sum(v);
    if ((t & 31) == 0) red[t >> 5] = v;
    __syncthreads();
    if (t < 8) {
        float x = red[t];
#pragma unroll
        for (int o = 4; o; o >>= 1) x += __shfl_xor_sync(0xffu, x, o);
        if (t == 0) red[0] = x;
    }
    __syncthreads();
    float r = red[0];
    __syncthreads();
    return r;
}

// ---------------- small builders ----------------
__global__ void rel_sum_kernel(const float* __restrict__ relation_emb) {
    int c = threadIdx.x;
    if (c < REL_D) {
        float s = 0.f;
#pragma unroll 4
        for (int r = 0; r < NRR; ++r) s += relation_emb[r * REL_D + c];
        g_rel_sum[c] = s;
    }
}

__global__ void build_inputs_kernel(const float* __restrict__ H,
                                    const float* __restrict__ entity_emb,
                                    const float* __restrict__ relation_emb,
                                    const int* __restrict__ e,
                                    const int* __restrict__ q,
                                    const int* __restrict__ pred_id) {
    int b = blockIdx.x;
    int t = threadIdx.x;
    int ei = e[b];
    int qi = q[b];
    int pi = pred_id[b];
    if (t < ENT_D)
        g_C1[b * 800 + t] = entity_emb[(size_t)ei * ENT_D + t];
    for (int c = t; c < HIST_D; c += 256)
        g_C1[b * 800 + 200 + c] = H[(size_t)b * HIST_D + c];
    if (t < REL_D)
        g_C1[b * 800 + 600 + t] = relation_emb[(size_t)qi * REL_D + t];
    if (t < ENT_D) {
        float pv = entity_emb[(size_t)pi * ENT_D + t];
        g_P[b * ENT_D + t] = pv;
        g_alpha_in[b * 400 + t] = g_rel_sum[t];
        g_alpha_in[b * 400 + 200 + t] = 400.0f * pv;  // NR * pred_emb
    }
}

// ---------------- tiled SGEMM: C[M,N] = A[M,K] @ W[N,K]^T + bias, optional ReLU ----------------
// 32x32 block tile, 2x2 per-thread register tile, 256 threads.
template <int RELU>
__global__ void __launch_bounds__(256, 4)
sgemm32(const float* __restrict__ Am, int lda,
        const float* __restrict__ W,
        const float* __restrict__ bias,
        float* __restrict__ C, int ldc,
        int M, int N, int K) {
    __shared__ float As[32][33];
    __shared__ float Bs[32][33];
    const int tid = threadIdx.x;
    const int tx = tid & 15;
    const int ty = tid >> 4;
    const int row0 = blockIdx.y * 32;
    const int col0 = blockIdx.x * 32;
    const int lr = tid >> 3;        // 0..31
    const int lc = (tid & 7) << 2;  // 0,4,...,28

    float acc00 = 0.f, acc01 = 0.f, acc10 = 0.f, acc11 = 0.f;

    for (int k0 = 0; k0 < K; k0 += 32) {
        int gk = k0 + lc;
        // A tile (K%4==0; rows 16B-aligned for all shapes here)
        {
            float4 v = make_float4(0.f, 0.f, 0.f, 0.f);
            int gr = row0 + lr;
            if (gr < M && gk < K)
                v = *reinterpret_cast<const float4*>(Am + (size_t)gr * lda + gk);
            As[lr][lc] = v.x; As[lr][lc + 1] = v.y; As[lr][lc + 2] = v.z; As[lr][lc + 3] = v.w;
        }
        // W tile
        {
            float4 v = make_float4(0.f, 0.f, 0.f, 0.f);
            int gn = col0 + lr;
            if (gn < N && gk < K)
                v = *reinterpret_cast<const float4*>(W + (size_t)gn * K + gk);
            Bs[lr][lc] = v.x; Bs[lr][lc + 1] = v.y; Bs[lr][lc + 2] = v.z; Bs[lr][lc + 3] = v.w;
        }
        __syncthreads();
#pragma unroll
        for (int k = 0; k < 32; ++k) {
            float a0 = As[ty * 2][k];
            float a1 = As[ty * 2 + 1][k];
            float b0 = Bs[tx * 2][k];
            float b1 = Bs[tx * 2 + 1][k];
            acc00 += a0 * b0; acc01 += a0 * b1;
            acc10 += a1 * b0; acc11 += a1 * b1;
        }
        __syncthreads();
    }

    int r0 = row0 + ty * 2;
    int c0 = col0 + tx * 2;
#pragma unroll
    for (int i = 0; i < 2; ++i) {
#pragma unroll
        for (int j = 0; j < 2; ++j) {
            int r = r0 + i, c = c0 + j;
            if (r < M && c < N) {
                float v = (i == 0 ? (j == 0 ? acc00 : acc01) : (j == 0 ? acc10 : acc11)) + bias[c];
                if (RELU) v = fmaxf(v, 0.f);
                C[(size_t)r * ldc + c] = v;
            }
        }
    }
}

// ---------------- beta: softmax(pred_ent_info @ relK^T) @ relation_emb ----------------
__global__ void __launch_bounds__(256)
beta_kernel(const float* __restrict__ relation_emb) {
    int b = blockIdx.x;
    int t = threadIdx.x;
    __shared__ float p[REL_D];
    __shared__ float la[NRR];
    __shared__ float red[8];

    if (t < REL_D) p[t] = g_PEI[b * REL_D + t];
    __syncthreads();

    for (int r = t; r < NRR; r += 256) {
        const float* kr = g_relK + r * REL_D;
        float s = 0.f;
#pragma unroll 8
        for (int k = 0; k < REL_D; ++k) s += p[k] * kr[k];
        la[r] = s;
    }
    __syncthreads();

    float m = -3.4e38f;
    for (int r = t; r < NRR; r += 256) m = fmaxf(m, la[r]);
    m = block_max256(m, red, t);

    float sum = 0.f;
    for (int r = t; r < NRR; r += 256) {
        float ev = expf(la[r] - m);
        la[r] = ev;
        sum += ev;
    }
    sum = block_sum256(sum, red, t);
    float inv = 1.f / sum;
    __syncthreads();

    if (t < REL_D) {
        float s = 0.f;
#pragma unroll 4
        for (int r = 0; r < NRR; ++r) s += la[r] * relation_emb[r * REL_D + t];
        g_AB[b * 400 + 200 + t] = s * inv;
    }
}

// ---------------- relation_att = softmax(ATT @ relation_emb^T) ----------------
__global__ void __launch_bounds__(256)
relatt_kernel(const float* __restrict__ relation_emb,
              float* __restrict__ out) {
    int b = blockIdx.x;
    int t = threadIdx.x;
    __shared__ float p[REL_D];
    __shared__ float la[NRR];
    __shared__ float red[8];

    if (t < REL_D) p[t] = g_ATT[b * REL_D + t];
    __syncthreads();

    for (int r = t; r < NRR; r += 256) {
        const float* kr = relation_emb + (size_t)r * REL_D;
        float s = 0.f;
#pragma unroll 8
        for (int k = 0; k < REL_D; ++k) s += p[k] * kr[k];
        la[r] = s;
    }
    __syncthreads();

    float m = -3.4e38f;
    for (int r = t; r < NRR; r += 256) m = fmaxf(m, la[r]);
    m = block_max256(m, red, t);

    float sum = 0.f;
    for (int r = t; r < NRR; r += 256) {
        float ev = expf(la[r] - m);
        la[r] = ev;
        sum += ev;
    }
    sum = block_sum256(sum, red, t);
    float inv = 1.f / sum;
    __syncthreads();

    for (int r = t; r < NRR; r += 256) out[(size_t)b * NRR + r] = la[r] * inv;
}

// ---------------- policy: gather scores, masked softmax, entropy ----------------
__global__ void __launch_bounds__(NA)
policy_kernel(const float* __restrict__ relation_emb,
              const float* __restrict__ entity_emb,
              const int* __restrict__ r_space,
              const int* __restrict__ e_space,
              const float* __restrict__ action_mask,
              float* __restrict__ action_dist,
              float* __restrict__ entropy_out) {
    int b = blockIdx.x;
    int t = threadIdx.x;  // one thread per action, blockDim = 256 = NA
    __shared__ float x2[ADIM_D];
    __shared__ float red[8];

    for (int c = t; c < ADIM_D; c += NA) x2[c] = g_XV[b * 600 + c];
    __syncthreads();

    int rs = r_space[(size_t)b * NA + t];
    int es = e_space[(size_t)b * NA + t];
    const float4* rrow = reinterpret_cast<const float4*>(relation_emb + (size_t)rs * REL_D);
    const float4* erow = reinterpret_cast<const float4*>(entity_emb + (size_t)es * ENT_D);

    float s = 0.f;
#pragma unroll 10
    for (int k = 0; k < REL_D / 4; ++k) {
        float4 v = rrow[k];
        s += v.x * x2[4 * k] + v.y * x2[4 * k + 1] + v.z * x2[4 * k + 2] + v.w * x2[4 * k + 3];
    }
#pragma unroll 10
    for (int k = 0; k < ENT_D / 4; ++k) {
        float4 v = erow[k];
        s += v.x * x2[200 + 4 * k] + v.y * x2[200 + 4 * k + 1] +
             v.z * x2[200 + 4 * k + 2] + v.w * x2[200 + 4 * k + 3];
    }
    float mask = action_mask[(size_t)b * NA + t];
    s -= (1.0f - mask) * 1e31f;

    float m = block_max256(s, red, t);
    float ev = expf(s - m);
    float sum = block_sum256(ev, red, t);
    float prob = ev / sum;
    action_dist[(size_t)b * NA + t] = prob;

    float h = block_sum256(-prob * logf(prob + 1e-20f), red, t);
    if (t == 0) entropy_out[b] = h;
}

// ---------------- launch ----------------
extern "C" void kernel_launch(void* const* d_in, const int* in_sizes, int n_in,
                              void* d_out, int out_size) {
    const float* H            = (const float*)d_in[0];
    const float* action_mask  = (const float*)d_in[1];
    const float* entity_emb   = (const float*)d_in[2];
    const float* relation_emb = (const float*)d_in[3];
    const float* W1 = (const float*)d_in[4];
    const float* b1 = (const float*)d_in[5];
    const float* W2 = (const float*)d_in[6];
    const float* b2 = (const float*)d_in[7];
    const float* W3 = (const float*)d_in[8];
    const float* b3 = (const float*)d_in[9];
    const float* W4 = (const float*)d_in[10];
    const float* b4 = (const float*)d_in[11];
    const float* W5 = (const float*)d_in[12];
    const float* b5 = (const float*)d_in[13];
    const float* W6 = (const float*)d_in[14];
    const float* b6 = (const float*)d_in[15];
    const float* Watt = (const float*)d_in[16];
    const float* batt = (const float*)d_in[17];
    const int* e       = (const int*)d_in[18];
    const int* q       = (const int*)d_in[19];
    const int* pred_id = (const int*)d_in[20];
    const int* r_space = (const int*)d_in[21];
    const int* e_space = (const int*)d_in[22];

    float* out = (float*)d_out;
    float* out_action_dist = out;                    // [512, 256]
    float* out_entropy     = out + NB * NA;          // [512]
    float* out_relatt      = out + NB * NA + NB;     // [512, 400]

    // Unconditional symbol-address queries every call: deterministic, no
    // static state (harness contract forbids static guards/caching).
    float *pC1, *pP, *pAin, *pRelK, *pX, *pXV, *pPEI, *pAB, *pATT;
    cudaGetSymbolAddress((void**)&pC1, g_C1);
    cudaGetSymbolAddress((void**)&pP, g_P);
    cudaGetSymbolAddress((void**)&pAin, g_alpha_in);
    cudaGetSymbolAddress((void**)&pRelK, g_relK);
    cudaGetSymbolAddress((void**)&pX, g_X);
    cudaGetSymbolAddress((void**)&pXV, g_XV);
    cudaGetSymbolAddress((void**)&pPEI, g_PEI);
    cudaGetSymbolAddress((void**)&pAB, g_AB);
    cudaGetSymbolAddress((void**)&pATT, g_ATT);

    // 1. rel_sum (independent)
    rel_sum_kernel<<<1, 256>>>(relation_emb);
    // 2. gathers + concat builders (needs rel_sum)
    build_inputs_kernel<<<NB, 256>>>(H, entity_emb, relation_emb, e, q, pred_id);
    // 3. relation_K = relation_emb @ W4^T + b4   [400,200]
    sgemm32<0><<<dim3(7, 13), 256>>>(relation_emb, 200, W4, b4, pRelK, 200, 400, 200, 200);
    // 4. X = relu(C1 @ W1^T + b1)   [512,400]
    sgemm32<1><<<dim3(13, 16), 256>>>(pC1, 800, W1, b1, pX, 400, 512, 400, 800);
    // 5. X2 = X @ W2^T + b2  -> XV[:, 0:400]
    sgemm32<0><<<dim3(13, 16), 256>>>(pX, 400, W2, b2, pXV, 600, 512, 400, 400);
    // 6. pred_ent_info = P @ W3^T + b3   [512,200]
    sgemm32<0><<<dim3(7, 16), 256>>>(pP, 200, W3, b3, pPEI, 200, 512, 200, 200);
    // 7. beta -> AB[:, 200:400]
    beta_kernel<<<NB, 256>>>(relation_emb);
    // 8. alpha = alpha_in @ W5^T + b5 -> AB[:, 0:200]
    sgemm32<0><<<dim3(7, 16), 256>>>(pAin, 400, W5, b5, pAB, 400, 512, 200, 400);
    // 9. V_A = AB @ W6^T + b6 -> XV[:, 400:600]
    sgemm32<0><<<dim3(7, 16), 256>>>(pAB, 400, W6, b6, pXV + 400, 600, 512, 200, 400);
    // 10. ATT = XV @ Watt^T + batt   [512,200]
    sgemm32<0><<<dim3(7, 16), 256>>>(pXV, 600, Watt, batt, pATT, 200, 512, 200, 600);
    // 11. relation_att = softmax(ATT @ relation_emb^T)
    relatt_kernel<<<NB, 256>>>(relation_emb, out_relatt);
    // 12. policy: scores gather + masked softmax + entropy
    policy_kernel<<<NB, NA>>>(relation_emb, entity_emb, r_space, e_space,
                              action_mask, out_action_dist, out_entropy);
}

// round 12
// speedup vs baseline: 1.5762x; 1.5762x over previous
#include <cuda_runtime.h>

#define NB    512      // batch
#define NEE   100000   // entities
#define NRR   400      // relations
#define NA    256      // actions
#define ENT_D 200
#define REL_D 200
#define HIST_D 400
#define ADIM_D 400

// ---------------- scratch (device globals; no allocation allowed) ----------------
__device__ __align__(16) float g_C1[NB * 800];        // [E | H | Q]
__device__ __align__(16) float g_P[NB * ENT_D];       // pred_emb gather
__device__ __align__(16) float g_alpha_in[NB * 400];  // [rel_sum | NR*pred]
__device__ __align__(16) float g_relK[NRR * REL_D];   // relation_emb @ W4^T + b4
__device__ __align__(16) float g_WattT[600 * REL_D];  // Watt^T [600,200]
__device__ __align__(16) float g_Wra[NRR * 600];      // relE @ Watt [400,600]
__device__ __align__(16) float g_M6T[REL_D * NRR];    // M6T[j][r] = sum_k relE[r][k]*W6[j][200+k]
__device__ __align__(16) float g_brel[NRR];           // batt . relE[r]
__device__ __align__(16) float g_rel_sum[REL_D];
__device__ __align__(16) float g_X[NB * ADIM_D];      // relu(l1)
__device__ __align__(16) float g_XV[NB * 600];        // [X2 (400) | V_A (200)]
__device__ __align__(16) float g_PEI[NB * REL_D];     // pred_ent_info
__device__ __align__(16) float g_AB[NB * 400];        // alpha in [:,0:200]
__device__ __align__(16) float g_LA[NB * NRR];        // local_att / RA logits (reused)
__device__ float g_zero[1024];                        // zero-init, never written

// ---------------- warp/block reduction helpers ----------------
__device__ __forceinline__ float warp_max(float v) {
#pragma unroll
    for (int o = 16; o; o >>= 1) v = fmaxf(v, __shfl_xor_sync(0xffffffffu, v, o));
    return v;
}
__device__ __forceinline__ float warp_sum(float v) {
#pragma unroll
    for (int o = 16; o; o >>= 1) v += __shfl_xor_sync(0xffffffffu, v, o);
    return v;
}
__device__ __forceinline__ float block_max256(float v, float* red, int t) {
    v = warp_max(v);
    if ((t & 31) == 0) red[t >> 5] = v;
    __syncthreads();
    if (t < 8) {
        float x = red[t];
#pragma unroll
        for (int o = 4; o; o >>= 1) x = fmaxf(x, __shfl_xor_sync(0xffu, x, o));
        if (t == 0) red[0] = x;
    }
    __syncthreads();
    float r = red[0];
    __syncthreads();
    return r;
}
__device__ __forceinline__ float block_sum256(float v, float* red, int t) {
    v = warp_sum(v);
    if ((t & 31) == 0) red[t >> 5] = v;
    __syncthreads();
    if (t < 8) {
        float x = red[t];
#pragma unroll
        for (int o = 4; o; o >>= 1) x += __shfl_xor_sync(0xffu, x, o);
        if (t == 0) red[0] = x;
    }
    __syncthreads();
    float r = red[0];
    __syncthreads();
    return r;
}

// ---------------- prep: relE colsum | brel | Watt transpose ----------------
// grid = 200 + 400 + 600 = 1200 blocks
__global__ void __launch_bounds__(256)
prep_kernel(const float* __restrict__ relation_emb,
            const float* __restrict__ Watt,
            const float* __restrict__ batt) {
    int bid = blockIdx.x;
    int t = threadIdx.x;
    if (bid < REL_D) {
        int c = bid;
        __shared__ float red[8];
        float s = 0.f;
        for (int r = t; r < NRR; r += 256)
            s += relation_emb[(size_t)r * REL_D + c];
        s = block_sum256(s, red, t);
        if (t == 0) g_rel_sum[c] = s;
    } else if (bid < REL_D + NRR) {
        int r = bid - REL_D;
        __shared__ float red[8];
        float s = (t < REL_D) ? batt[t] * relation_emb[(size_t)r * REL_D + t] : 0.f;
        s = block_sum256(s, red, t);
        if (t == 0) g_brel[r] = s;
    } else {
        int j = bid - (REL_D + NRR);
        if (t < REL_D) g_WattT[(size_t)j * REL_D + t] = Watt[(size_t)t * 600 + j];
    }
}

// ---------------- gathers + concat builders ----------------
__global__ void __launch_bounds__(256)
build_inputs_kernel(const float* __restrict__ H,
                    const float* __restrict__ entity_emb,
                    const float* __restrict__ relation_emb,
                    const int* __restrict__ e,
                    const int* __restrict__ q,
                    const int* __restrict__ pred_id) {
    int b = blockIdx.x;
    int t = threadIdx.x;
    int ei = e[b];
    int qi = q[b];
    int pi = pred_id[b];
    if (t < ENT_D)
        g_C1[b * 800 + t] = entity_emb[(size_t)ei * ENT_D + t];
    for (int c = t; c < HIST_D; c += 256)
        g_C1[b * 800 + 200 + c] = H[(size_t)b * HIST_D + c];
    if (t < REL_D)
        g_C1[b * 800 + 600 + t] = relation_emb[(size_t)qi * REL_D + t];
    if (t < ENT_D) {
        float pv = entity_emb[(size_t)pi * ENT_D + t];
        g_P[b * ENT_D + t] = pv;
        g_alpha_in[b * 400 + t] = g_rel_sum[t];
        g_alpha_in[b * 400 + 200 + t] = 400.0f * pv;  // NR * pred_emb
    }
}

// ---------------- GEMM descriptors (shared by both tile sizes) ----------------
// C[M,N] = [C +] A[M,K] @ W^T + bias (optional ReLU). W row n at W + n*ldw.
struct GDesc {
    const float* A;
    const float* W;
    const float* bias;
    float* C;
    int lda, ldw, ldc, M, N, K, relu, accum, gx, off;
};
struct GBatch {
    GDesc d[6];
    int n;
};

// ---------------- batched SGEMM, 32x32 tile, 2x2/thread (serial-tail GEMMs) ----------------
__global__ void __launch_bounds__(256, 4)
sgemm_batched(GBatch gb) {
    int blk = blockIdx.x;
    int i = 0;
#pragma unroll
    for (int j = 1; j < 6; ++j)
        if (j < gb.n && blk >= gb.d[j].off) i = j;
    const GDesc d = gb.d[i];
    int rel = blk - d.off;
    int bx = rel % d.gx;
    int by = rel / d.gx;

    __shared__ float As[32][33];
    __shared__ float Bs[32][33];
    const int tid = threadIdx.x;
    const int tx = tid & 15;
    const int ty = tid >> 4;
    const int row0 = by * 32;
    const int col0 = bx * 32;
    const int lr = tid >> 3;
    const int lc = (tid & 7) << 2;

    float acc00 = 0.f, acc01 = 0.f, acc10 = 0.f, acc11 = 0.f;

    for (int k0 = 0; k0 < d.K; k0 += 32) {
        int gk = k0 + lc;
        {
            float4 v = make_float4(0.f, 0.f, 0.f, 0.f);
            int gr = row0 + lr;
            if (gr < d.M && gk < d.K)
                v = *reinterpret_cast<const float4*>(d.A + (size_t)gr * d.lda + gk);
            As[lr][lc] = v.x; As[lr][lc + 1] = v.y; As[lr][lc + 2] = v.z; As[lr][lc + 3] = v.w;
        }
        {
            float4 v = make_float4(0.f, 0.f, 0.f, 0.f);
            int gn = col0 + lr;
            if (gn < d.N && gk < d.K)
                v = *reinterpret_cast<const float4*>(d.W + (size_t)gn * d.ldw + gk);
            Bs[lr][lc] = v.x; Bs[lr][lc + 1] = v.y; Bs[lr][lc + 2] = v.z; Bs[lr][lc + 3] = v.w;
        }
        __syncthreads();
#pragma unroll
        for (int k = 0; k < 32; ++k) {
            float a0 = As[ty * 2][k];
            float a1 = As[ty * 2 + 1][k];
            float b0 = Bs[tx * 2][k];
            float b1 = Bs[tx * 2 + 1][k];
            acc00 += a0 * b0; acc01 += a0 * b1;
            acc10 += a1 * b0; acc11 += a1 * b1;
        }
        __syncthreads();
    }

    int r0 = row0 + ty * 2;
    int c0 = col0 + tx * 2;
#pragma unroll
    for (int ii = 0; ii < 2; ++ii) {
#pragma unroll
        for (int jj = 0; jj < 2; ++jj) {
            int r = r0 + ii, c = c0 + jj;
            if (r < d.M && c < d.N) {
                float v = (ii == 0 ? (jj == 0 ? acc00 : acc01) : (jj == 0 ? acc10 : acc11)) + d.bias[c];
                if (d.accum) v += d.C[(size_t)r * d.ldc + c];
                if (d.relu) v = fmaxf(v, 0.f);
                d.C[(size_t)r * d.ldc + c] = v;
            }
        }
    }
}

// ---------------- batched SGEMM, 64x64 tile, 4x4/thread (big parallel batches) ----------------
// Smem stored k-major (As[k][row]) so compute reads are LDS.128.
__global__ void __launch_bounds__(256, 2)
sgemm64_batched(GBatch gb) {
    int blk = blockIdx.x;
    int i = 0;
#pragma unroll
    for (int j = 1; j < 6; ++j)
        if (j < gb.n && blk >= gb.d[j].off) i = j;
    const GDesc d = gb.d[i];
    int rel = blk - d.off;
    int bx = rel % d.gx;
    int by = rel / d.gx;

    __shared__ __align__(16) float As[16][68];
    __shared__ __align__(16) float Bs[16][68];
    const int tid = threadIdx.x;
    const int tx = tid & 15;        // n quad
    const int ty = tid >> 4;        // m quad
    const int row0 = by * 64;
    const int col0 = bx * 64;
    const int lrow = tid >> 2;      // 0..63
    const int lk = (tid & 3) << 2;  // 0,4,8,12

    float acc[4][4];
#pragma unroll
    for (int a = 0; a < 4; ++a)
#pragma unroll
        for (int b = 0; b < 4; ++b) acc[a][b] = 0.f;

    for (int k0 = 0; k0 < d.K; k0 += 16) {
        int gk = k0 + lk;
        {
            float4 v = make_float4(0.f, 0.f, 0.f, 0.f);
            int gr = row0 + lrow;
            if (gr < d.M && gk < d.K)
                v = *reinterpret_cast<const float4*>(d.A + (size_t)gr * d.lda + gk);
            As[lk][lrow] = v.x; As[lk + 1][lrow] = v.y; As[lk + 2][lrow] = v.z; As[lk + 3][lrow] = v.w;
        }
        {
            float4 v = make_float4(0.f, 0.f, 0.f, 0.f);
            int gn = col0 + lrow;
            if (gn < d.N && gk < d.K)
                v = *reinterpret_cast<const float4*>(d.W + (size_t)gn * d.ldw + gk);
            Bs[lk][lrow] = v.x; Bs[lk + 1][lrow] = v.y; Bs[lk + 2][lrow] = v.z; Bs[lk + 3][lrow] = v.w;
        }
        __syncthreads();
#pragma unroll
        for (int k = 0; k < 16; ++k) {
            float4 a4 = *reinterpret_cast<const float4*>(&As[k][ty * 4]);
            float4 b4 = *reinterpret_cast<const float4*>(&Bs[k][tx * 4]);
            float av[4] = {a4.x, a4.y, a4.z, a4.w};
            float bv[4] = {b4.x, b4.y, b4.z, b4.w};
#pragma unroll
            for (int a = 0; a < 4; ++a)
#pragma unroll
                for (int b = 0; b < 4; ++b) acc[a][b] += av[a] * bv[b];
        }
        __syncthreads();
    }

#pragma unroll
    for (int a = 0; a < 4; ++a) {
        int r = row0 + ty * 4 + a;
        if (r < d.M) {
#pragma unroll
            for (int b = 0; b < 4; ++b) {
                int c = col0 + tx * 4 + b;
                if (c < d.N) {
                    float v = acc[a][b] + d.bias[c];
                    if (d.accum) v += d.C[(size_t)r * d.ldc + c];
                    if (d.relu) v = fmaxf(v, 0.f);
                    d.C[(size_t)r * d.ldc + c] = v;
                }
            }
        }
    }
}

// ---------------- row softmax over 400 cols (block per row) ----------------
__global__ void __launch_bounds__(256)
rowsoftmax400_kernel(const float* __restrict__ in, float* __restrict__ out) {
    int b = blockIdx.x;
    int t = threadIdx.x;
    __shared__ float red[8];
    float v0 = (t < NRR) ? in[(size_t)b * NRR + t] : -3.4e38f;
    int t2 = t + 256;
    float v1 = (t2 < NRR) ? in[(size_t)b * NRR + t2] : -3.4e38f;

    float m = block_max256(fmaxf(v0, v1), red, t);
    float e0 = (t < NRR) ? expf(v0 - m) : 0.f;
    float e1 = (t2 < NRR) ? expf(v1 - m) : 0.f;
    float sum = block_sum256(e0 + e1, red, t);
    float inv = 1.f / sum;
    if (t < NRR) out[(size_t)b * NRR + t] = e0 * inv;
    if (t2 < NRR) out[(size_t)b * NRR + t2] = e1 * inv;
}

// ---------------- fused tail: relation_att softmax (blocks 0..NB-1) + policy (blocks NB..2NB-1) ----------------
__global__ void __launch_bounds__(256)
tail_kernel(const float* __restrict__ la,
            float* __restrict__ out_relatt,
            const float* __restrict__ relation_emb,
            const float* __restrict__ entity_emb,
            const int* __restrict__ r_space,
            const int* __restrict__ e_space,
            const float* __restrict__ action_mask,
            float* __restrict__ action_dist,
            float* __restrict__ entropy_out) {
    int t = threadIdx.x;
    __shared__ float red[8];
    if (blockIdx.x < NB) {
        // relation_att = softmax(LA row)
        int b = blockIdx.x;
        float v0 = (t < NRR) ? la[(size_t)b * NRR + t] : -3.4e38f;
        int t2 = t + 256;
        float v1 = (t2 < NRR) ? la[(size_t)b * NRR + t2] : -3.4e38f;

        float m = block_max256(fmaxf(v0, v1), red, t);
        float e0 = (t < NRR) ? expf(v0 - m) : 0.f;
        float e1 = (t2 < NRR) ? expf(v1 - m) : 0.f;
        float sum = block_sum256(e0 + e1, red, t);
        float inv = 1.f / sum;
        if (t < NRR) out_relatt[(size_t)b * NRR + t] = e0 * inv;
        if (t2 < NRR) out_relatt[(size_t)b * NRR + t2] = e1 * inv;
    } else {
        // policy: gather scores, masked softmax, entropy
        int b = blockIdx.x - NB;
        __shared__ float x2[ADIM_D];
        for (int c = t; c < ADIM_D; c += 256) x2[c] = g_XV[b * 600 + c];
        __syncthreads();

        int rs = r_space[(size_t)b * NA + t];
        int es = e_space[(size_t)b * NA + t];
        const float4* rrow = reinterpret_cast<const float4*>(relation_emb + (size_t)rs * REL_D);
        const float4* erow = reinterpret_cast<const float4*>(entity_emb + (size_t)es * ENT_D);

        float s = 0.f;
#pragma unroll 10
        for (int k = 0; k < REL_D / 4; ++k) {
            float4 v = rrow[k];
            s += v.x * x2[4 * k] + v.y * x2[4 * k + 1] + v.z * x2[4 * k + 2] + v.w * x2[4 * k + 3];
        }
#pragma unroll 10
        for (int k = 0; k < ENT_D / 4; ++k) {
            float4 v = erow[k];
            s += v.x * x2[200 + 4 * k] + v.y * x2[200 + 4 * k + 1] +
                 v.z * x2[200 + 4 * k + 2] + v.w * x2[200 + 4 * k + 3];
        }
        float mask = action_mask[(size_t)b * NA + t];
        s -= (1.0f - mask) * 1e31f;

        float m = block_max256(s, red, t);
        float ev = expf(s - m);
        float sum = block_sum256(ev, red, t);
        float prob = ev / sum;
        action_dist[(size_t)b * NA + t] = prob;

        float h = block_sum256(-prob * logf(prob + 1e-20f), red, t);
        if (t == 0) entropy_out[b] = h;
    }
}

// ---------------- launch ----------------
extern "C" void kernel_launch(void* const* d_in, const int* in_sizes, int n_in,
                              void* d_out, int out_size) {
    const float* H            = (const float*)d_in[0];
    const float* action_mask  = (const float*)d_in[1];
    const float* entity_emb   = (const float*)d_in[2];
    const float* relation_emb = (const float*)d_in[3];
    const float* W1 = (const float*)d_in[4];
    const float* b1 = (const float*)d_in[5];
    const float* W2 = (const float*)d_in[6];
    const float* b2 = (const float*)d_in[7];
    const float* W3 = (const float*)d_in[8];
    const float* b3 = (const float*)d_in[9];
    const float* W4 = (const float*)d_in[10];
    const float* b4 = (const float*)d_in[11];
    const float* W5 = (const float*)d_in[12];
    const float* b5 = (const float*)d_in[13];
    const float* W6 = (const float*)d_in[14];
    const float* b6 = (const float*)d_in[15];
    const float* Watt = (const float*)d_in[16];
    const float* batt = (const float*)d_in[17];
    const int* e       = (const int*)d_in[18];
    const int* q       = (const int*)d_in[19];
    const int* pred_id = (const int*)d_in[20];
    const int* r_space = (const int*)d_in[21];
    const int* e_space = (const int*)d_in[22];

    float* out = (float*)d_out;
    float* out_action_dist = out;                    // [512, 256]
    float* out_entropy     = out + NB * NA;          // [512]
    float* out_relatt      = out + NB * NA + NB;     // [512, 400]

    float *pC1, *pP, *pAin, *pRelK, *pWattT, *pWra, *pM6T, *pBrel,
          *pX, *pXV, *pPEI, *pAB, *pLA, *pZero;
    cudaGetSymbolAddress((void**)&pC1, g_C1);
    cudaGetSymbolAddress((void**)&pP, g_P);
    cudaGetSymbolAddress((void**)&pAin, g_alpha_in);
    cudaGetSymbolAddress((void**)&pRelK, g_relK);
    cudaGetSymbolAddress((void**)&pWattT, g_WattT);
    cudaGetSymbolAddress((void**)&pWra, g_Wra);
    cudaGetSymbolAddress((void**)&pM6T, g_M6T);
    cudaGetSymbolAddress((void**)&pBrel, g_brel);
    cudaGetSymbolAddress((void**)&pX, g_X);
    cudaGetSymbolAddress((void**)&pXV, g_XV);
    cudaGetSymbolAddress((void**)&pPEI, g_PEI);
    cudaGetSymbolAddress((void**)&pAB, g_AB);
    cudaGetSymbolAddress((void**)&pLA, g_LA);
    cudaGetSymbolAddress((void**)&pZero, g_zero);

    // 1. prep: rel_sum | brel | Watt transpose  (1200 blocks)
    prep_kernel<<<1200, 256>>>(relation_emb, Watt, batt);
    // 2. gathers + concat builders
    build_inputs_kernel<<<NB, 256>>>(H, entity_emb, relation_emb, e, q, pred_id);

    // 3. batch A (64-tile): relK | X(relu) | PEI | alpha | Wra | M6T   (246 blocks)
    {
        GBatch gb;
        //          A             W       bias   C      lda  ldw  ldc  M    N    K   rl ac gx  off
        gb.d[0] = {relation_emb, W4,     b4,    pRelK, 200, 200, 200, 400, 200, 200, 0, 0, 4, 0};
        gb.d[1] = {pC1,          W1,     b1,    pX,    800, 800, 400, 512, 400, 800, 1, 0, 7, 28};
        gb.d[2] = {pP,           W3,     b3,    pPEI,  200, 200, 200, 512, 200, 200, 0, 0, 4, 84};
        gb.d[3] = {pAin,         W5,     b5,    pAB,   400, 400, 400, 512, 200, 400, 0, 0, 4, 116};
        gb.d[4] = {relation_emb, pWattT, pZero, pWra,  200, 200, 600, 400, 600, 200, 0, 0, 10, 148};
        gb.d[5] = {W6 + 200,     relation_emb, pZero, pM6T, 400, 200, 400, 200, 400, 200, 0, 0, 7, 218};
        gb.n = 6;
        sgemm64_batched<<<246, 256>>>(gb);
    }
    // 4. batch B (64-tile): X2 | LA = PEI @ relK^T | alpha@W6L^T + b6 -> XV[:,400:600]  (144 blocks)
    {
        GBatch gb;
        gb.d[0] = {pX,   W2,    b2,    pXV,        400, 400, 600, 512, 400, 400, 0, 0, 7, 0};
        gb.d[1] = {pPEI, pRelK, pZero, pLA,        200, 200, 400, 512, 400, 200, 0, 0, 7, 56};
        gb.d[2] = {pAB,  W6,    b6,    pXV + 400,  400, 400, 600, 512, 200, 200, 0, 0, 4, 112};
        gb.d[3] = gb.d[0]; gb.d[4] = gb.d[0]; gb.d[5] = gb.d[0];
        gb.n = 3;
        sgemm64_batched<<<144, 256>>>(gb);
    }
    // 5. softmax over LA rows (in place)
    rowsoftmax400_kernel<<<NB, 256>>>(pLA, pLA);
    // 6. V_A beta part: XV[:,400:600] += softmax(LA) @ M6T^T-form  (32-tile, accum)
    {
        GBatch gb;
        gb.d[0] = {pLA, pM6T, pZero, pXV + 400, 400, 400, 600, 512, 200, 400, 0, 1, 7, 0};
        gb.d[1] = gb.d[0]; gb.d[2] = gb.d[0]; gb.d[3] = gb.d[0]; gb.d[4] = gb.d[0]; gb.d[5] = gb.d[0];
        gb.n = 1;
        sgemm_batched<<<112, 256>>>(gb);
    }
    // 7. RA logits = XV @ Wra^T + brel -> LA   (32-tile; ATT folded into Wra)
    {
        GBatch gb;
        gb.d[0] = {pXV, pWra, pBrel, pLA, 600, 600, 400, 512, 400, 600, 0, 0, 13, 0};
        gb.d[1] = gb.d[0]; gb.d[2] = gb.d[0]; gb.d[3] = gb.d[0]; gb.d[4] = gb.d[0]; gb.d[5] = gb.d[0];
        gb.n = 1;
        sgemm_batched<<<208, 256>>>(gb);
    }
    // 8. fused tail: relation_att softmax + policy (1024 blocks)
    tail_kernel<<<2 * NB, 256>>>(pLA, out_relatt, relation_emb, entity_emb,
                                 r_space, e_space, action_mask,
                                 out_action_dist, out_entropy);
}

// round 17
// speedup vs baseline: 1.6472x; 1.0451x over previous
#include <cuda_runtime.h>

#define NB    512      // batch
#define NEE   100000   // entities
#define NRR   400      // relations
#define NA    256      // actions
#define ENT_D 200
#define REL_D 200
#define HIST_D 400
#define ADIM_D 400

// ---------------- scratch (device globals; no allocation allowed) ----------------
__device__ __align__(16) float g_C1[NB * 800];        // [E | H | Q]
__device__ __align__(16) float g_P[NB * ENT_D];       // pred_emb gather
__device__ __align__(16) float g_alpha_in[NB * 400];  // [rel_sum | NR*pred]
__device__ __align__(16) float g_relK[NRR * REL_D];   // relation_emb @ W4^T + b4
__device__ __align__(16) float g_WattT[600 * REL_D];  // Watt^T [600,200]
__device__ __align__(16) float g_Wra[NRR * 600];      // relE @ Watt [400,600]
__device__ __align__(16) float g_M6T[REL_D * NRR];    // M6T[j][r] = sum_k relE[r][k]*W6[j][200+k]
__device__ __align__(16) float g_brel[NRR];           // batt . relE[r]
__device__ __align__(16) float g_rel_sum[REL_D];
__device__ __align__(16) float g_X[NB * ADIM_D];      // relu(l1)
__device__ __align__(16) float g_XV[NB * 600];        // [X2 (400) | V_A (200)]
__device__ __align__(16) float g_PEI[NB * REL_D];     // pred_ent_info
__device__ __align__(16) float g_AB[NB * 400];        // alpha in [:,0:200]
__device__ __align__(16) float g_LA[NB * NRR];        // local_att / RA logits (reused)
__device__ float g_zero[1024];                        // zero-init, never written

// ---------------- warp/block reduction helpers ----------------
__device__ __forceinline__ float warp_max(float v) {
#pragma unroll
    for (int o = 16; o; o >>= 1) v = fmaxf(v, __shfl_xor_sync(0xffffffffu, v, o));
    return v;
}
__device__ __forceinline__ float warp_sum(float v) {
#pragma unroll
    for (int o = 16; o; o >>= 1) v += __shfl_xor_sync(0xffffffffu, v, o);
    return v;
}
__device__ __forceinline__ float block_max256(float v, float* red, int t) {
    v = warp_max(v);
    if ((t & 31) == 0) red[t >> 5] = v;
    __syncthreads();
    if (t < 8) {
        float x = red[t];
#pragma unroll
        for (int o = 4; o; o >>= 1) x = fmaxf(x, __shfl_xor_sync(0xffu, x, o));
        if (t == 0) red[0] = x;
    }
    __syncthreads();
    float r = red[0];
    __syncthreads();
    return r;
}
__device__ __forceinline__ float block_sum256(float v, float* red, int t) {
    v = warp_sum(v);
    if ((t & 31) == 0) red[t >> 5] = v;
    __syncthreads();
    if (t < 8) {
        float x = red[t];
#pragma unroll
        for (int o = 4; o; o >>= 1) x += __shfl_xor_sync(0xffu, x, o);
        if (t == 0) red[0] = x;
    }
    __syncthreads();
    float r = red[0];
    __syncthreads();
    return r;
}

// ---------------- prep: relE colsum | brel | Watt transpose ----------------
__global__ void __launch_bounds__(256)
prep_kernel(const float* __restrict__ relation_emb,
            const float* __restrict__ Watt,
            const float* __restrict__ batt) {
    int bid = blockIdx.x;
    int t = threadIdx.x;
    if (bid < REL_D) {
        int c = bid;
        __shared__ float red[8];
        float s = 0.f;
        for (int r = t; r < NRR; r += 256)
            s += relation_emb[(size_t)r * REL_D + c];
        s = block_sum256(s, red, t);
        if (t == 0) g_rel_sum[c] = s;
    } else if (bid < REL_D + NRR) {
        int r = bid - REL_D;
        __shared__ float red[8];
        float s = (t < REL_D) ? batt[t] * relation_emb[(size_t)r * REL_D + t] : 0.f;
        s = block_sum256(s, red, t);
        if (t == 0) g_brel[r] = s;
    } else {
        int j = bid - (REL_D + NRR);
        if (t < REL_D) g_WattT[(size_t)j * REL_D + t] = Watt[(size_t)t * 600 + j];
    }
}

// ---------------- gathers + concat builders ----------------
__global__ void __launch_bounds__(256)
build_inputs_kernel(const float* __restrict__ H,
                    const float* __restrict__ entity_emb,
                    const float* __restrict__ relation_emb,
                    const int* __restrict__ e,
                    const int* __restrict__ q,
                    const int* __restrict__ pred_id) {
    int b = blockIdx.x;
    int t = threadIdx.x;
    int ei = e[b];
    int qi = q[b];
    int pi = pred_id[b];
    if (t < ENT_D)
        g_C1[b * 800 + t] = entity_emb[(size_t)ei * ENT_D + t];
    for (int c = t; c < HIST_D; c += 256)
        g_C1[b * 800 + 200 + c] = H[(size_t)b * HIST_D + c];
    if (t < REL_D)
        g_C1[b * 800 + 600 + t] = relation_emb[(size_t)qi * REL_D + t];
    if (t < ENT_D) {
        float pv = entity_emb[(size_t)pi * ENT_D + t];
        g_P[b * ENT_D + t] = pv;
        g_alpha_in[b * 400 + t] = g_rel_sum[t];
        g_alpha_in[b * 400 + 200 + t] = 400.0f * pv;  // NR * pred_emb
    }
}

// ---------------- GEMM descriptors (shared by both tile sizes) ----------------
// C[M,N] = [C +] A[M,K] @ W^T + bias (optional ReLU). W row n at W + n*ldw.
struct GDesc {
    const float* A;
    const float* W;
    const float* bias;
    float* C;
    int lda, ldw, ldc, M, N, K, relu, accum, gx, off;
};
struct GBatch {
    GDesc d[6];
    int n;
};

// ---------------- batched SGEMM, 32x32 tile, 2x2/thread, double-buffered ----------------
__global__ void __launch_bounds__(256, 4)
sgemm_batched(GBatch gb) {
    int blk = blockIdx.x;
    int i = 0;
#pragma unroll
    for (int j = 1; j < 6; ++j)
        if (j < gb.n && blk >= gb.d[j].off) i = j;
    const GDesc d = gb.d[i];
    int rel = blk - d.off;
    int bx = rel % d.gx;
    int by = rel / d.gx;

    __shared__ float As[32][33];
    __shared__ float Bs[32][33];
    const int tid = threadIdx.x;
    const int tx = tid & 15;
    const int ty = tid >> 4;
    const int row0 = by * 32;
    const int col0 = bx * 32;
    const int lr = tid >> 3;
    const int lc = (tid & 7) << 2;
    const int gr = row0 + lr;   // A row this thread loads
    const int gn = col0 + lr;   // W row this thread loads

    float acc00 = 0.f, acc01 = 0.f, acc10 = 0.f, acc11 = 0.f;

    // prefetch tile 0 into registers
    float4 a_pre = make_float4(0.f, 0.f, 0.f, 0.f);
    float4 b_pre = make_float4(0.f, 0.f, 0.f, 0.f);
    {
        int gk = lc;
        if (gr < d.M && gk < d.K)
            a_pre = *reinterpret_cast<const float4*>(d.A + (size_t)gr * d.lda + gk);
        if (gn < d.N && gk < d.K)
            b_pre = *reinterpret_cast<const float4*>(d.W + (size_t)gn * d.ldw + gk);
    }

    for (int k0 = 0; k0 < d.K; k0 += 32) {
        As[lr][lc] = a_pre.x; As[lr][lc + 1] = a_pre.y; As[lr][lc + 2] = a_pre.z; As[lr][lc + 3] = a_pre.w;
        Bs[lr][lc] = b_pre.x; Bs[lr][lc + 1] = b_pre.y; Bs[lr][lc + 2] = b_pre.z; Bs[lr][lc + 3] = b_pre.w;
        __syncthreads();

        // prefetch next tile (overlaps with compute below)
        a_pre = make_float4(0.f, 0.f, 0.f, 0.f);
        b_pre = make_float4(0.f, 0.f, 0.f, 0.f);
        int kn = k0 + 32;
        if (kn < d.K) {
            int gk = kn + lc;
            if (gr < d.M && gk < d.K)
                a_pre = *reinterpret_cast<const float4*>(d.A + (size_t)gr * d.lda + gk);
            if (gn < d.N && gk < d.K)
                b_pre = *reinterpret_cast<const float4*>(d.W + (size_t)gn * d.ldw + gk);
        }

#pragma unroll
        for (int k = 0; k < 32; ++k) {
            float a0 = As[ty * 2][k];
            float a1 = As[ty * 2 + 1][k];
            float b0 = Bs[tx * 2][k];
            float b1 = Bs[tx * 2 + 1][k];
            acc00 += a0 * b0; acc01 += a0 * b1;
            acc10 += a1 * b0; acc11 += a1 * b1;
        }
        __syncthreads();
    }

    int r0 = row0 + ty * 2;
    int c0 = col0 + tx * 2;
#pragma unroll
    for (int ii = 0; ii < 2; ++ii) {
#pragma unroll
        for (int jj = 0; jj < 2; ++jj) {
            int r = r0 + ii, c = c0 + jj;
            if (r < d.M && c < d.N) {
                float v = (ii == 0 ? (jj == 0 ? acc00 : acc01) : (jj == 0 ? acc10 : acc11)) + d.bias[c];
                if (d.accum) v += d.C[(size_t)r * d.ldc + c];
                if (d.relu) v = fmaxf(v, 0.f);
                d.C[(size_t)r * d.ldc + c] = v;
            }
        }
    }
}

// ---------------- batched SGEMM, 64x64 tile, 4x4/thread, double-buffered ----------------
// Smem stored k-major (As[k][row]) so compute reads are LDS.128.
__global__ void __launch_bounds__(256, 2)
sgemm64_batched(GBatch gb) {
    int blk = blockIdx.x;
    int i = 0;
#pragma unroll
    for (int j = 1; j < 6; ++j)
        if (j < gb.n && blk >= gb.d[j].off) i = j;
    const GDesc d = gb.d[i];
    int rel = blk - d.off;
    int bx = rel % d.gx;
    int by = rel / d.gx;

    __shared__ __align__(16) float As[16][68];
    __shared__ __align__(16) float Bs[16][68];
    const int tid = threadIdx.x;
    const int tx = tid & 15;        // n quad
    const int ty = tid >> 4;        // m quad
    const int row0 = by * 64;
    const int col0 = bx * 64;
    const int lrow = tid >> 2;      // 0..63
    const int lk = (tid & 3) << 2;  // 0,4,8,12
    const int gr = row0 + lrow;
    const int gn = col0 + lrow;

    float acc[4][4];
#pragma unroll
    for (int a = 0; a < 4; ++a)
#pragma unroll
        for (int b = 0; b < 4; ++b) acc[a][b] = 0.f;

    // prefetch tile 0 into registers
    float4 a_pre = make_float4(0.f, 0.f, 0.f, 0.f);
    float4 b_pre = make_float4(0.f, 0.f, 0.f, 0.f);
    {
        int gk = lk;
        if (gr < d.M && gk < d.K)
            a_pre = *reinterpret_cast<const float4*>(d.A + (size_t)gr * d.lda + gk);
        if (gn < d.N && gk < d.K)
            b_pre = *reinterpret_cast<const float4*>(d.W + (size_t)gn * d.ldw + gk);
    }

    for (int k0 = 0; k0 < d.K; k0 += 16) {
        As[lk][lrow] = a_pre.x; As[lk + 1][lrow] = a_pre.y; As[lk + 2][lrow] = a_pre.z; As[lk + 3][lrow] = a_pre.w;
        Bs[lk][lrow] = b_pre.x; Bs[lk + 1][lrow] = b_pre.y; Bs[lk + 2][lrow] = b_pre.z; Bs[lk + 3][lrow] = b_pre.w;
        __syncthreads();

        // prefetch next tile (overlaps with compute below)
        a_pre = make_float4(0.f, 0.f, 0.f, 0.f);
        b_pre = make_float4(0.f, 0.f, 0.f, 0.f);
        int kn = k0 + 16;
        if (kn < d.K) {
            int gk = kn + lk;
            if (gr < d.M && gk < d.K)
                a_pre = *reinterpret_cast<const float4*>(d.A + (size_t)gr * d.lda + gk);
            if (gn < d.N && gk < d.K)
                b_pre = *reinterpret_cast<const float4*>(d.W + (size_t)gn * d.ldw + gk);
        }

#pragma unroll
        for (int k = 0; k < 16; ++k) {
            float4 a4 = *reinterpret_cast<const float4*>(&As[k][ty * 4]);
            float4 b4 = *reinterpret_cast<const float4*>(&Bs[k][tx * 4]);
            float av[4] = {a4.x, a4.y, a4.z, a4.w};
            float bv[4] = {b4.x, b4.y, b4.z, b4.w};
#pragma unroll
            for (int a = 0; a < 4; ++a)
#pragma unroll
                for (int b = 0; b < 4; ++b) acc[a][b] += av[a] * bv[b];
        }
        __syncthreads();
    }

#pragma unroll
    for (int a = 0; a < 4; ++a) {
        int r = row0 + ty * 4 + a;
        if (r < d.M) {
#pragma unroll
            for (int b = 0; b < 4; ++b) {
                int c = col0 + tx * 4 + b;
                if (c < d.N) {
                    float v = acc[a][b] + d.bias[c];
                    if (d.accum) v += d.C[(size_t)r * d.ldc + c];
                    if (d.relu) v = fmaxf(v, 0.f);
                    d.C[(size_t)r * d.ldc + c] = v;
                }
            }
        }
    }
}

// ---------------- row softmax over 400 cols (block per row) ----------------
__global__ void __launch_bounds__(256)
rowsoftmax400_kernel(const float* __restrict__ in, float* __restrict__ out) {
    int b = blockIdx.x;
    int t = threadIdx.x;
    __shared__ float red[8];
    float v0 = (t < NRR) ? in[(size_t)b * NRR + t] : -3.4e38f;
    int t2 = t + 256;
    float v1 = (t2 < NRR) ? in[(size_t)b * NRR + t2] : -3.4e38f;

    float m = block_max256(fmaxf(v0, v1), red, t);
    float e0 = (t < NRR) ? expf(v0 - m) : 0.f;
    float e1 = (t2 < NRR) ? expf(v1 - m) : 0.f;
    float sum = block_sum256(e0 + e1, red, t);
    float inv = 1.f / sum;
    if (t < NRR) out[(size_t)b * NRR + t] = e0 * inv;
    if (t2 < NRR) out[(size_t)b * NRR + t2] = e1 * inv;
}

// ---------------- fused tail: relation_att softmax (blocks 0..NB-1) + policy (blocks NB..2NB-1) ----------------
__global__ void __launch_bounds__(256)
tail_kernel(const float* __restrict__ la,
            float* __restrict__ out_relatt,
            const float* __restrict__ relation_emb,
            const float* __restrict__ entity_emb,
            const int* __restrict__ r_space,
            const int* __restrict__ e_space,
            const float* __restrict__ action_mask,
            float* __restrict__ action_dist,
            float* __restrict__ entropy_out) {
    int t = threadIdx.x;
    __shared__ float red[8];
    if (blockIdx.x < NB) {
        // relation_att = softmax(LA row)
        int b = blockIdx.x;
        float v0 = (t < NRR) ? la[(size_t)b * NRR + t] : -3.4e38f;
        int t2 = t + 256;
        float v1 = (t2 < NRR) ? la[(size_t)b * NRR + t2] : -3.4e38f;

        float m = block_max256(fmaxf(v0, v1), red, t);
        float e0 = (t < NRR) ? expf(v0 - m) : 0.f;
        float e1 = (t2 < NRR) ? expf(v1 - m) : 0.f;
        float sum = block_sum256(e0 + e1, red, t);
        float inv = 1.f / sum;
        if (t < NRR) out_relatt[(size_t)b * NRR + t] = e0 * inv;
        if (t2 < NRR) out_relatt[(size_t)b * NRR + t2] = e1 * inv;
    } else {
        // policy: gather scores, masked softmax, entropy
        int b = blockIdx.x - NB;
        __shared__ float x2[ADIM_D];
        for (int c = t; c < ADIM_D; c += 256) x2[c] = g_XV[b * 600 + c];
        __syncthreads();

        int rs = r_space[(size_t)b * NA + t];
        int es = e_space[(size_t)b * NA + t];
        const float4* rrow = reinterpret_cast<const float4*>(relation_emb + (size_t)rs * REL_D);
        const float4* erow = reinterpret_cast<const float4*>(entity_emb + (size_t)es * ENT_D);

        float s = 0.f;
#pragma unroll 10
        for (int k = 0; k < REL_D / 4; ++k) {
            float4 v = rrow[k];
            s += v.x * x2[4 * k] + v.y * x2[4 * k + 1] + v.z * x2[4 * k + 2] + v.w * x2[4 * k + 3];
        }
#pragma unroll 10
        for (int k = 0; k < ENT_D / 4; ++k) {
            float4 v = erow[k];
            s += v.x * x2[200 + 4 * k] + v.y * x2[200 + 4 * k + 1] +
                 v.z * x2[200 + 4 * k + 2] + v.w * x2[200 + 4 * k + 3];
        }
        float mask = action_mask[(size_t)b * NA + t];
        s -= (1.0f - mask) * 1e31f;

        float m = block_max256(s, red, t);
        float ev = expf(s - m);
        float sum = block_sum256(ev, red, t);
        float prob = ev / sum;
        action_dist[(size_t)b * NA + t] = prob;

        float h = block_sum256(-prob * logf(prob + 1e-20f), red, t);
        if (t == 0) entropy_out[b] = h;
    }
}

// ---------------- launch ----------------
extern "C" void kernel_launch(void* const* d_in, const int* in_sizes, int n_in,
                              void* d_out, int out_size) {
    const float* H            = (const float*)d_in[0];
    const float* action_mask  = (const float*)d_in[1];
    const float* entity_emb   = (const float*)d_in[2];
    const float* relation_emb = (const float*)d_in[3];
    const float* W1 = (const float*)d_in[4];
    const float* b1 = (const float*)d_in[5];
    const float* W2 = (const float*)d_in[6];
    const float* b2 = (const float*)d_in[7];
    const float* W3 = (const float*)d_in[8];
    const float* b3 = (const float*)d_in[9];
    const float* W4 = (const float*)d_in[10];
    const float* b4 = (const float*)d_in[11];
    const float* W5 = (const float*)d_in[12];
    const float* b5 = (const float*)d_in[13];
    const float* W6 = (const float*)d_in[14];
    const float* b6 = (const float*)d_in[15];
    const float* Watt = (const float*)d_in[16];
    const float* batt = (const float*)d_in[17];
    const int* e       = (const int*)d_in[18];
    const int* q       = (const int*)d_in[19];
    const int* pred_id = (const int*)d_in[20];
    const int* r_space = (const int*)d_in[21];
    const int* e_space = (const int*)d_in[22];

    float* out = (float*)d_out;
    float* out_action_dist = out;                    // [512, 256]
    float* out_entropy     = out + NB * NA;          // [512]
    float* out_relatt      = out + NB * NA + NB;     // [512, 400]

    float *pC1, *pP, *pAin, *pRelK, *pWattT, *pWra, *pM6T, *pBrel,
          *pX, *pXV, *pPEI, *pAB, *pLA, *pZero;
    cudaGetSymbolAddress((void**)&pC1, g_C1);
    cudaGetSymbolAddress((void**)&pP, g_P);
    cudaGetSymbolAddress((void**)&pAin, g_alpha_in);
    cudaGetSymbolAddress((void**)&pRelK, g_relK);
    cudaGetSymbolAddress((void**)&pWattT, g_WattT);
    cudaGetSymbolAddress((void**)&pWra, g_Wra);
    cudaGetSymbolAddress((void**)&pM6T, g_M6T);
    cudaGetSymbolAddress((void**)&pBrel, g_brel);
    cudaGetSymbolAddress((void**)&pX, g_X);
    cudaGetSymbolAddress((void**)&pXV, g_XV);
    cudaGetSymbolAddress((void**)&pPEI, g_PEI);
    cudaGetSymbolAddress((void**)&pAB, g_AB);
    cudaGetSymbolAddress((void**)&pLA, g_LA);
    cudaGetSymbolAddress((void**)&pZero, g_zero);

    // 1. prep: rel_sum | brel | Watt transpose  (1200 blocks)
    prep_kernel<<<1200, 256>>>(relation_emb, Watt, batt);
    // 2. gathers + concat builders
    build_inputs_kernel<<<NB, 256>>>(H, entity_emb, relation_emb, e, q, pred_id);

    // 3. batch A (64-tile): relK | X(relu) | PEI | alpha | Wra | M6T   (246 blocks)
    {
        GBatch gb;
        //          A             W       bias   C      lda  ldw  ldc  M    N    K   rl ac gx  off
        gb.d[0] = {relation_emb, W4,     b4,    pRelK, 200, 200, 200, 400, 200, 200, 0, 0, 4, 0};
        gb.d[1] = {pC1,          W1,     b1,    pX,    800, 800, 400, 512, 400, 800, 1, 0, 7, 28};
        gb.d[2] = {pP,           W3,     b3,    pPEI,  200, 200, 200, 512, 200, 200, 0, 0, 4, 84};
        gb.d[3] = {pAin,         W5,     b5,    pAB,   400, 400, 400, 512, 200, 400, 0, 0, 4, 116};
        gb.d[4] = {relation_emb, pWattT, pZero, pWra,  200, 200, 600, 400, 600, 200, 0, 0, 10, 148};
        gb.d[5] = {W6 + 200,     relation_emb, pZero, pM6T, 400, 200, 400, 200, 400, 200, 0, 0, 7, 218};
        gb.n = 6;
        sgemm64_batched<<<246, 256>>>(gb);
    }
    // 4. batch B (64-tile): X2 | LA = PEI @ relK^T | alpha@W6L^T + b6 -> XV[:,400:600]  (144 blocks)
    {
        GBatch gb;
        gb.d[0] = {pX,   W2,    b2,    pXV,        400, 400, 600, 512, 400, 400, 0, 0, 7, 0};
        gb.d[1] = {pPEI, pRelK, pZero, pLA,        200, 200, 400, 512, 400, 200, 0, 0, 7, 56};
        gb.d[2] = {pAB,  W6,    b6,    pXV + 400,  400, 400, 600, 512, 200, 200, 0, 0, 4, 112};
        gb.d[3] = gb.d[0]; gb.d[4] = gb.d[0]; gb.d[5] = gb.d[0];
        gb.n = 3;
        sgemm64_batched<<<144, 256>>>(gb);
    }
    // 5. softmax over LA rows (in place)
    rowsoftmax400_kernel<<<NB, 256>>>(pLA, pLA);
    // 6. V_A beta part: XV[:,400:600] += softmax(LA) @ M6T^T-form  (32-tile, accum)
    {
        GBatch gb;
        gb.d[0] = {pLA, pM6T, pZero, pXV + 400, 400, 400, 600, 512, 200, 400, 0, 1, 7, 0};
        gb.d[1] = gb.d[0]; gb.d[2] = gb.d[0]; gb.d[3] = gb.d[0]; gb.d[4] = gb.d[0]; gb.d[5] = gb.d[0];
        gb.n = 1;
        sgemm_batched<<<112, 256>>>(gb);
    }
    // 7. RA logits = XV @ Wra^T + brel -> LA   (32-tile; ATT folded into Wra)
    {
        GBatch gb;
        gb.d[0] = {pXV, pWra, pBrel, pLA, 600, 600, 400, 512, 400, 600, 0, 0, 13, 0};
        gb.d[1] = gb.d[0]; gb.d[2] = gb.d[0]; gb.d[3] = gb.d[0]; gb.d[4] = gb.d[0]; gb.d[5] = gb.d[0];
        gb.n = 1;
        sgemm_batched<<<208, 256>>>(gb);
    }
    // 8. fused tail: relation_att softmax + policy (1024 blocks)
    tail_kernel<<<2 * NB, 256>>>(pLA, out_relatt, relation_emb, entity_emb,
                                 r_space, e_space, action_mask,
                                 out_action_dist, out_entropy);
}